// round 14
// baseline (speedup 1.0000x reference)
#include <cuda_runtime.h>
#include <cuda_fp16.h>
#include <cstdint>

#define D_DIM  448
#define MTOT   32768
#define BM     128
#define BN     112
#define BK     64
#define AS     72                          // A smem stride in floats (v2 conflict-free)
#define BSB    160                         // B smem row stride in BYTES (v2 conflict-free)
#define A_STAGE_BYTES (BM * AS * 4)        // 36864
#define B_STAGE_BYTES (BN * BSB)           // 17920
#define STG_BYTES (A_STAGE_BYTES + B_STAGE_BYTES)   // 54784
#define SMEM_BYTES (2 * STG_BYTES)         // 109568 -> 2 CTAs/SM
#define NT_W   196                         // 14x14 weff tiles

// W_eff transposed [n][k_perm16] as fp16 (k16-interleave: one 8B smem load
// yields both b-fragments of a k16 mma step).
__device__ __align__(16) __half g_Wh[D_DIM * D_DIM];
__device__ int g_ctrs[2];                        // {work pool, done count}
__device__ const int g_zeros[2] = {0, 0};        // memcpy-D2D reset source

// ---- helpers ----------------------------------------------------------------
__device__ __forceinline__ uint32_t smem_u32(const void* p) {
    uint32_t a;
    asm("{ .reg .u64 t; cvta.to.shared.u64 t, %1; cvt.u32.u64 %0, t; }" : "=r"(a) : "l"(p));
    return a;
}
__device__ __forceinline__ uint32_t pack_h2(float lo, float hi) {
    __half2 h = __floats2half2_rn(lo, hi);
    return *reinterpret_cast<uint32_t*>(&h);
}
__device__ __forceinline__ void mma_f16(float* c, const uint32_t* a, uint32_t b0, uint32_t b1) {
    asm volatile(
        "mma.sync.aligned.m16n8k16.row.col.f32.f16.f16.f32 "
        "{%0,%1,%2,%3}, {%4,%5,%6,%7}, {%8,%9}, {%0,%1,%2,%3};"
        : "+f"(c[0]), "+f"(c[1]), "+f"(c[2]), "+f"(c[3])
        : "r"(a[0]), "r"(a[1]), "r"(a[2]), "r"(a[3]), "r"(b0), "r"(b1));
}
#define CP16(dst, src) \
    asm volatile("cp.async.cg.shared.global [%0], [%1], 16;" :: "r"(dst), "l"(src) : "memory")
#define CP_COMMIT() asm volatile("cp.async.commit_group;" ::: "memory")
#define CP_WAIT0()  asm volatile("cp.async.wait_group 0;" ::: "memory")

// ---------------------------------------------------------------------------
// Fused kernel: phase 1 issues A-stage-0 loads, phase 2 work-steals W_eff
// 32x32 tiles (fp16, k16-interleaved into g_Wh), phase 3 spins on the done
// counter, phase 4 runs the R13 fp16 HMMA mainloop.
// ---------------------------------------------------------------------------
__global__ void __launch_bounds__(256, 2) fused_kernel(
    const float* __restrict__ x,  const float* __restrict__ Wq,
    const float* __restrict__ Wk, const float* __restrict__ Wv,
    const float* __restrict__ Wo, const float* __restrict__ Ad,
    const float* __restrict__ Bd, const float* __restrict__ Cd,
    float* __restrict__ out) {
    extern __shared__ __align__(16) char smem[];
    __shared__ int s_tile;

    const int tid   = threadIdx.x;
    const int wid   = tid >> 5;
    const int lane  = tid & 31;
    const int g     = lane >> 2;
    const int t     = lane & 3;
    const int warpM = wid & 3;
    const int warpN = wid >> 2;

    const int m0 = blockIdx.y * BM;
    const int n0 = blockIdx.x * BN;

    const uint32_t smem_base = smem_u32(smem);

    // ---- phase 1: issue A-stage-0 cp.async (x only; independent of W) ------
    {
        const uint32_t aBase = smem_base;   // stage 0
#pragma unroll
        for (int j = 0; j < 8; j++) {
            const int id  = tid + j * 256;
            const int row = id >> 4;
            const int c   = id & 15;
            CP16(aBase + (uint32_t)(row * (AS * 4) + c * 16),
                 x + (size_t)(m0 + row) * D_DIM + c * 4);
        }
    }

    // ---- phase 2: work-steal W_eff tiles (smem scratch in stage-1 region) --
    {
        float* dgp = reinterpret_cast<float*>(smem + STG_BYTES);        // 3*448 floats
        float (*Ms)[33] = reinterpret_cast<float(*)[33]>(smem + STG_BYTES + 5376);
        float (*Ws)[33] = reinterpret_cast<float(*)[33]>(smem + STG_BYTES + 5376 + 4224);
        const int ty2  = tid >> 4, tx2 = tid & 15;
        const int lrow = tid >> 3;
        const int lc4  = (tid & 7) * 4;
        bool dg_loaded = false;

        for (;;) {
            if (tid == 0) s_tile = atomicAdd(&g_ctrs[0], 1);
            __syncthreads();
            const int tile = s_tile;
            if (tile >= NT_W) break;

            if (!dg_loaded) {               // CTA-uniform branch
                for (int i = tid; i < D_DIM; i += 256) {
                    dgp[i]              = Ad[(size_t)i * D_DIM + i];
                    dgp[D_DIM + i]      = Bd[(size_t)i * D_DIM + i];
                    dgp[2 * D_DIM + i]  = Cd[(size_t)i * D_DIM + i];
                }
                dg_loaded = true;
            }

            const int by = tile / 14;
            const int bx = tile - by * 14;
            const int k0w = by * 32, n0w = bx * 32;
            const size_t qoff = (size_t)(k0w + lrow) * D_DIM + lc4;
            const size_t ooff = (size_t)lrow * D_DIM + n0w + lc4;

            float4 pq = *reinterpret_cast<const float4*>(Wq + qoff);
            float4 pk = *reinterpret_cast<const float4*>(Wk + qoff);
            float4 pv = *reinterpret_cast<const float4*>(Wv + qoff);
            float4 po = *reinterpret_cast<const float4*>(Wo + ooff);
            __syncthreads();   // dg stores visible; prev tile reads done

            float acw[2][2] = {};
            for (int kt = 0; kt < D_DIM; kt += 32) {
                {
                    const float4 da = *reinterpret_cast<const float4*>(&dgp[kt + lc4]);
                    const float4 db = *reinterpret_cast<const float4*>(&dgp[D_DIM + kt + lc4]);
                    const float4 dc = *reinterpret_cast<const float4*>(&dgp[2 * D_DIM + kt + lc4]);
                    Ms[lrow][lc4 + 0] = pq.x * da.x + pk.x * db.x + pv.x * dc.x;
                    Ms[lrow][lc4 + 1] = pq.y * da.y + pk.y * db.y + pv.y * dc.y;
                    Ms[lrow][lc4 + 2] = pq.z * da.z + pk.z * db.z + pv.z * dc.z;
                    Ms[lrow][lc4 + 3] = pq.w * da.w + pk.w * db.w + pv.w * dc.w;
                    Ws[lrow][lc4 + 0] = po.x; Ws[lrow][lc4 + 1] = po.y;
                    Ws[lrow][lc4 + 2] = po.z; Ws[lrow][lc4 + 3] = po.w;
                }
                __syncthreads();
                if (kt + 32 < D_DIM) {
                    pq = *reinterpret_cast<const float4*>(Wq + qoff + kt + 32);
                    pk = *reinterpret_cast<const float4*>(Wk + qoff + kt + 32);
                    pv = *reinterpret_cast<const float4*>(Wv + qoff + kt + 32);
                    po = *reinterpret_cast<const float4*>(Wo + ooff + (size_t)(kt + 32) * D_DIM);
                }
#pragma unroll
                for (int kk = 0; kk < 32; kk++) {
                    const float a0 = Ms[ty2][kk],      a1 = Ms[ty2 + 16][kk];
                    const float b0 = Ws[kk][tx2],      b1 = Ws[kk][tx2 + 16];
                    acw[0][0] += a0 * b0; acw[0][1] += a0 * b1;
                    acw[1][0] += a1 * b0; acw[1][1] += a1 * b1;
                }
                __syncthreads();
            }
#pragma unroll
            for (int i = 0; i < 2; i++) {
                const int k = k0w + ty2 + i * 16;
                const int j = k & 15;
                const int kp = (k & ~15) | (4 * ((j & 7) >> 1) + 2 * (j >> 3) + (j & 1));
#pragma unroll
                for (int jj = 0; jj < 2; jj++) {
                    const int n = n0w + tx2 + jj * 16;
                    g_Wh[(size_t)n * D_DIM + kp] = __float2half_rn(acw[i][jj]);
                }
            }
            __threadfence();
            __syncthreads();
            if (tid == 0) atomicAdd(&g_ctrs[1], 1);
        }
    }

    // ---- phase 3: wait for all W_eff tiles --------------------------------
    if (tid == 0) {
        volatile int* dp = &g_ctrs[1];
        while (*dp < NT_W) { }
    }
    __syncthreads();
    __threadfence();

    // ---- phase 4: fp16 HMMA GEMM (R13 mainloop) ----------------------------
    float acc[2][7][4];
#pragma unroll
    for (int i = 0; i < 2; i++)
#pragma unroll
        for (int j = 0; j < 7; j++)
#pragma unroll
            for (int q = 0; q < 4; q++) acc[i][j][q] = 0.f;

    auto load_A = [&](int s, int kt) {
        const uint32_t aBase = smem_base + (uint32_t)(s * STG_BYTES);
#pragma unroll
        for (int j = 0; j < 8; j++) {
            const int id  = tid + j * 256;
            const int row = id >> 4;
            const int c   = id & 15;
            CP16(aBase + (uint32_t)(row * (AS * 4) + c * 16),
                 x + (size_t)(m0 + row) * D_DIM + kt + c * 4);
        }
    };
    auto load_B = [&](int s, int kt) {
        const uint32_t bBase = smem_base + (uint32_t)(s * STG_BYTES) + (uint32_t)A_STAGE_BYTES;
#pragma unroll
        for (int j = 0; j < 3; j++) {
            const int id  = tid + j * 256;
            const int row = id >> 3;
            const int c   = id & 7;
            CP16(bBase + (uint32_t)(row * BSB + c * 16),
                 (const char*)g_Wh + ((size_t)(n0 + row) * D_DIM + kt) * 2 + c * 16);
        }
        if (tid < 128) {
            const int id  = tid + 768;
            const int row = id >> 3;
            const int c   = id & 7;
            CP16(bBase + (uint32_t)(row * BSB + c * 16),
                 (const char*)g_Wh + ((size_t)(n0 + row) * D_DIM + kt) * 2 + c * 16);
        }
    };

    load_B(0, 0);            // A stage 0 already issued in phase 1
    CP_COMMIT();

    const int NIT = D_DIM / BK;   // 7
#pragma unroll 1
    for (int it = 0; it < NIT; it++) {
        CP_WAIT0();
        __syncthreads();

        if (it + 1 < NIT) { load_A((it + 1) & 1, (it + 1) * BK); load_B((it + 1) & 1, (it + 1) * BK); }
        CP_COMMIT();

        const char* stage = smem + (it & 1) * STG_BYTES;
        const float* Arow = reinterpret_cast<const float*>(stage) + (warpM * 32 + g) * AS;
        const char* Brow  = stage + A_STAGE_BYTES + (warpN * 56 + g) * BSB;

#pragma unroll
        for (int kk2 = 0; kk2 < 4; kk2++) {
            const int k0 = kk2 * 16;
            uint32_t af[2][4];
#pragma unroll
            for (int mi = 0; mi < 2; mi++) {
                const float* Ar = Arow + mi * 16 * AS;
                const float2 x0 = *reinterpret_cast<const float2*>(Ar + k0 + 2 * t);
                const float2 x1 = *reinterpret_cast<const float2*>(Ar + 8 * AS + k0 + 2 * t);
                const float2 x2 = *reinterpret_cast<const float2*>(Ar + k0 + 2 * t + 8);
                const float2 x3 = *reinterpret_cast<const float2*>(Ar + 8 * AS + k0 + 2 * t + 8);
                af[mi][0] = pack_h2(x0.x, x0.y);
                af[mi][1] = pack_h2(x1.x, x1.y);
                af[mi][2] = pack_h2(x2.x, x2.y);
                af[mi][3] = pack_h2(x3.x, x3.y);
            }
#pragma unroll
            for (int ni = 0; ni < 7; ni++) {
                const uint2 bv = *reinterpret_cast<const uint2*>(
                    Brow + ni * 8 * BSB + kk2 * 32 + 8 * t);
                mma_f16(acc[0][ni], af[0], bv.x, bv.y);
                mma_f16(acc[1][ni], af[1], bv.x, bv.y);
            }
        }
    }

    // ---- epilogue ----------------------------------------------------------
#pragma unroll
    for (int mi = 0; mi < 2; mi++) {
        const int r0 = m0 + warpM * 32 + mi * 16 + g;
#pragma unroll
        for (int ni = 0; ni < 7; ni++) {
            const int c0 = n0 + warpN * 56 + ni * 8 + 2 * t;
            float2 v0, v1;
            v0.x = acc[mi][ni][0]; v0.y = acc[mi][ni][1];
            v1.x = acc[mi][ni][2]; v1.y = acc[mi][ni][3];
            *reinterpret_cast<float2*>(out + (size_t)r0 * D_DIM + c0)       = v0;
            *reinterpret_cast<float2*>(out + (size_t)(r0 + 8) * D_DIM + c0) = v1;
        }
    }
}

// ---------------------------------------------------------------------------
extern "C" void kernel_launch(void* const* d_in, const int* in_sizes, int n_in,
                              void* d_out, int out_size) {
    const float* x  = (const float*)d_in[0];
    const float* Wq = (const float*)d_in[1];
    const float* Wk = (const float*)d_in[2];
    const float* Wv = (const float*)d_in[3];
    const float* Wo = (const float*)d_in[4];
    const float* A  = (const float*)d_in[5];
    const float* B  = (const float*)d_in[6];
    const float* C  = (const float*)d_in[7];

    static void* ctr_addr = nullptr;
    static void* zero_addr = nullptr;
    if (!ctr_addr) {
        cudaGetSymbolAddress(&ctr_addr, g_ctrs);
        cudaGetSymbolAddress(&zero_addr, g_zeros);
        cudaFuncSetAttribute(fused_kernel, cudaFuncAttributeMaxDynamicSharedMemorySize,
                             SMEM_BYTES);
    }

    // reset work/done counters (D2D async copy: graph-capturable, no alloc)
    cudaMemcpyAsync(ctr_addr, zero_addr, 2 * sizeof(int), cudaMemcpyDeviceToDevice, 0);

    fused_kernel<<<dim3(D_DIM / BN, MTOT / BM), 256, SMEM_BYTES>>>(
        x, Wq, Wk, Wv, Wo, A, B, C, (float*)d_out);
}

// round 15
// speedup vs baseline: 1.1835x; 1.1835x over previous
#include <cuda_runtime.h>
#include <cuda_fp16.h>
#include <cstdint>

#define D_DIM  448
#define MTOT   32768
#define BM     128
#define BN     112
#define BK     64
#define NSTG   2
#define AS     72                          // A smem stride in floats (v2 conflict-free)
#define BSB    160                         // B smem row stride in BYTES (v2 conflict-free)
#define A_STAGE_BYTES (BM * AS * 4)        // 36864
#define B_STAGE_BYTES (BN * BSB)           // 17920
#define STG_BYTES (A_STAGE_BYTES + B_STAGE_BYTES)   // 54784
#define SMEM_BYTES (NSTG * STG_BYTES)      // 109568 -> 2 CTAs/SM

// W_eff transposed [n][k_perm16] as fp16.
// k16-interleave: j=k&15 -> p = 4*((j&7)>>1) + 2*(j>>3) + (j&1): one 8B load at
// half-offset 4t yields b0={k0+2t,2t+1} (low 4B) and b1={k0+2t+8,2t+9} (high 4B).
__device__ __align__(16) __half g_Wh[D_DIM * D_DIM];

// ---- helpers ----------------------------------------------------------------
__device__ __forceinline__ uint32_t smem_u32(const void* p) {
    uint32_t a;
    asm("{ .reg .u64 t; cvta.to.shared.u64 t, %1; cvt.u32.u64 %0, t; }" : "=r"(a) : "l"(p));
    return a;
}
__device__ __forceinline__ uint32_t pack_h2(float lo, float hi) {
    __half2 h = __floats2half2_rn(lo, hi);
    return *reinterpret_cast<uint32_t*>(&h);
}
__device__ __forceinline__ void mma_f16(float* c, const uint32_t* a, uint32_t b0, uint32_t b1) {
    asm volatile(
        "mma.sync.aligned.m16n8k16.row.col.f32.f16.f16.f32 "
        "{%0,%1,%2,%3}, {%4,%5,%6,%7}, {%8,%9}, {%0,%1,%2,%3};"
        : "+f"(c[0]), "+f"(c[1]), "+f"(c[2]), "+f"(c[3])
        : "r"(a[0]), "r"(a[1]), "r"(a[2]), "r"(a[3]), "r"(b0), "r"(b1));
}
#define CP16(dst, src) \
    asm volatile("cp.async.cg.shared.global [%0], [%1], 16;" :: "r"(dst), "l"(src) : "memory")
#define CP_COMMIT() asm volatile("cp.async.commit_group;" ::: "memory")
#define CP_WAIT0()  asm volatile("cp.async.wait_group 0;" ::: "memory")

// ---------------------------------------------------------------------------
// Prep: W_eff = (Wq*diagA + Wk*diagB + Wv*diagC) @ Wo, transposed +
// k16-interleaved + fp16 into g_Wh. 32x32 tiles, grid (14,14), 256 threads.
// NEW: 2-deep register prefetch (loads for iter i+2 issued at iter i) to
// fully cover L2/DRAM latency (~600cyc) with ~2 compute blocks (~900cyc).
// ---------------------------------------------------------------------------
__global__ void __launch_bounds__(256) weff_kernel(const float* __restrict__ Wq,
                                                   const float* __restrict__ Wk,
                                                   const float* __restrict__ Wv,
                                                   const float* __restrict__ Wo,
                                                   const float* __restrict__ A,
                                                   const float* __restrict__ Bm,
                                                   const float* __restrict__ C) {
    __shared__ float dg[3][D_DIM];
    __shared__ float Ms[32][33];
    __shared__ float Ws[32][33];
    const int tid = threadIdx.x;
    for (int i = tid; i < D_DIM; i += 256) {
        dg[0][i] = A[(size_t)i * D_DIM + i];
        dg[1][i] = Bm[(size_t)i * D_DIM + i];
        dg[2][i] = C[(size_t)i * D_DIM + i];
    }

    const int ty = tid >> 4, tx = tid & 15;
    const int k0 = blockIdx.y * 32;
    const int n0 = blockIdx.x * 32;
    const int lrow = tid >> 3;
    const int lc4  = (tid & 7) * 4;

    const size_t qoff = (size_t)(k0 + lrow) * D_DIM + lc4;
    const size_t ooff = (size_t)lrow * D_DIM + n0 + lc4;

    // 2-deep register prefetch buffers
    float4 pq[2], pk[2], pv[2], po[2];
#pragma unroll
    for (int s = 0; s < 2; s++) {
        pq[s] = *reinterpret_cast<const float4*>(Wq + qoff + s * 32);
        pk[s] = *reinterpret_cast<const float4*>(Wk + qoff + s * 32);
        pv[s] = *reinterpret_cast<const float4*>(Wv + qoff + s * 32);
        po[s] = *reinterpret_cast<const float4*>(Wo + ooff + (size_t)(s * 32) * D_DIM);
    }
    __syncthreads();   // covers dg[] stores

    float acc[2][2] = {};
    int idx = 0;
    for (int kt = 0; kt < D_DIM; kt += 32, idx ^= 1) {
        {
            const float4 da = *reinterpret_cast<const float4*>(&dg[0][kt + lc4]);
            const float4 db = *reinterpret_cast<const float4*>(&dg[1][kt + lc4]);
            const float4 dc = *reinterpret_cast<const float4*>(&dg[2][kt + lc4]);
            const float4 q = pq[idx], k = pk[idx], v = pv[idx], o = po[idx];
            Ms[lrow][lc4 + 0] = q.x * da.x + k.x * db.x + v.x * dc.x;
            Ms[lrow][lc4 + 1] = q.y * da.y + k.y * db.y + v.y * dc.y;
            Ms[lrow][lc4 + 2] = q.z * da.z + k.z * db.z + v.z * dc.z;
            Ms[lrow][lc4 + 3] = q.w * da.w + k.w * db.w + v.w * dc.w;
            Ws[lrow][lc4 + 0] = o.x; Ws[lrow][lc4 + 1] = o.y;
            Ws[lrow][lc4 + 2] = o.z; Ws[lrow][lc4 + 3] = o.w;
        }
        __syncthreads();

        // prefetch iter kt+64 into the slot just consumed
        if (kt + 64 < D_DIM) {
            pq[idx] = *reinterpret_cast<const float4*>(Wq + qoff + kt + 64);
            pk[idx] = *reinterpret_cast<const float4*>(Wk + qoff + kt + 64);
            pv[idx] = *reinterpret_cast<const float4*>(Wv + qoff + kt + 64);
            po[idx] = *reinterpret_cast<const float4*>(Wo + ooff + (size_t)(kt + 64) * D_DIM);
        }

#pragma unroll
        for (int kk = 0; kk < 32; kk++) {
            const float a0 = Ms[ty][kk],      a1 = Ms[ty + 16][kk];
            const float b0 = Ws[kk][tx],      b1 = Ws[kk][tx + 16];
            acc[0][0] += a0 * b0; acc[0][1] += a0 * b1;
            acc[1][0] += a1 * b0; acc[1][1] += a1 * b1;
        }
        __syncthreads();
    }
#pragma unroll
    for (int i = 0; i < 2; i++) {
        const int k = k0 + ty + i * 16;
        const int j = k & 15;
        const int kp = (k & ~15) | (4 * ((j & 7) >> 1) + 2 * (j >> 3) + (j & 1));
#pragma unroll
        for (int jj = 0; jj < 2; jj++) {
            const int n = n0 + tx + jj * 16;
            g_Wh[(size_t)n * D_DIM + kp] = __float2half_rn(acc[i][jj]);
        }
    }
}

// ---------------------------------------------------------------------------
// Main GEMM (R13, measured best): out = x @ W_eff via fp16 mma.sync m16n8k16.
// BM=128, BN=112, BK=64 -> 7 mainloop iterations. NSTG=2 double buffer:
// wait0 -> sync -> prefetch(it+1) -> compute(it). 256 threads (8 warps,
// 4m x 2n), warp tile 32x56.
// ---------------------------------------------------------------------------
__global__ void __launch_bounds__(256, 2) gemm_f16_kernel(const float* __restrict__ x,
                                                          float* __restrict__ out) {
    extern __shared__ __align__(16) char smem[];

    const int tid   = threadIdx.x;
    const int wid   = tid >> 5;
    const int lane  = tid & 31;
    const int g     = lane >> 2;
    const int t     = lane & 3;
    const int warpM = wid & 3;
    const int warpN = wid >> 2;

    const int m0 = blockIdx.y * BM;
    const int n0 = blockIdx.x * BN;

    const uint32_t smem_base = smem_u32(smem);

    float acc[2][7][4];
#pragma unroll
    for (int i = 0; i < 2; i++)
#pragma unroll
        for (int j = 0; j < 7; j++)
#pragma unroll
            for (int q = 0; q < 4; q++) acc[i][j][q] = 0.f;

    auto load_stage = [&](int s, int kt) {
        const uint32_t aBase = smem_base + (uint32_t)(s * STG_BYTES);
        const uint32_t bBase = aBase + (uint32_t)A_STAGE_BYTES;
#pragma unroll
        for (int j = 0; j < 8; j++) {
            const int id  = tid + j * 256;
            const int row = id >> 4;
            const int c   = id & 15;
            CP16(aBase + (uint32_t)(row * (AS * 4) + c * 16),
                 x + (size_t)(m0 + row) * D_DIM + kt + c * 4);
        }
#pragma unroll
        for (int j = 0; j < 3; j++) {
            const int id  = tid + j * 256;
            const int row = id >> 3;
            const int c   = id & 7;
            CP16(bBase + (uint32_t)(row * BSB + c * 16),
                 (const char*)g_Wh + ((size_t)(n0 + row) * D_DIM + kt) * 2 + c * 16);
        }
        if (tid < 128) {
            const int id  = tid + 768;
            const int row = id >> 3;
            const int c   = id & 7;
            CP16(bBase + (uint32_t)(row * BSB + c * 16),
                 (const char*)g_Wh + ((size_t)(n0 + row) * D_DIM + kt) * 2 + c * 16);
        }
    };

    load_stage(0, 0);
    CP_COMMIT();

    const int NIT = D_DIM / BK;   // 7
#pragma unroll 1
    for (int it = 0; it < NIT; it++) {
        CP_WAIT0();
        __syncthreads();

        if (it + 1 < NIT) load_stage((it + 1) & 1, (it + 1) * BK);
        CP_COMMIT();

        const char* stage = smem + (it & 1) * STG_BYTES;
        const float* Arow = reinterpret_cast<const float*>(stage)
                            + (warpM * 32 + g) * AS;
        const char* Brow  = stage + A_STAGE_BYTES + (warpN * 56 + g) * BSB;

#pragma unroll
        for (int kk2 = 0; kk2 < 4; kk2++) {    // four k16 blocks per BK=64
            const int k0 = kk2 * 16;
            uint32_t af[2][4];
#pragma unroll
            for (int mi = 0; mi < 2; mi++) {
                const float* Ar = Arow + mi * 16 * AS;
                const float2 x0 = *reinterpret_cast<const float2*>(Ar + k0 + 2 * t);
                const float2 x1 = *reinterpret_cast<const float2*>(Ar + 8 * AS + k0 + 2 * t);
                const float2 x2 = *reinterpret_cast<const float2*>(Ar + k0 + 2 * t + 8);
                const float2 x3 = *reinterpret_cast<const float2*>(Ar + 8 * AS + k0 + 2 * t + 8);
                af[mi][0] = pack_h2(x0.x, x0.y);
                af[mi][1] = pack_h2(x1.x, x1.y);
                af[mi][2] = pack_h2(x2.x, x2.y);
                af[mi][3] = pack_h2(x3.x, x3.y);
            }
#pragma unroll
            for (int ni = 0; ni < 7; ni++) {
                const uint2 bv = *reinterpret_cast<const uint2*>(
                    Brow + ni * 8 * BSB + kk2 * 32 + 8 * t);
                mma_f16(acc[0][ni], af[0], bv.x, bv.y);
                mma_f16(acc[1][ni], af[1], bv.x, bv.y);
            }
        }
    }

    // ---- epilogue: rows (g, g+8), cols (2t, 2t+1) per (mi, ni)
#pragma unroll
    for (int mi = 0; mi < 2; mi++) {
        const int r0 = m0 + warpM * 32 + mi * 16 + g;
#pragma unroll
        for (int ni = 0; ni < 7; ni++) {
            const int c0 = n0 + warpN * 56 + ni * 8 + 2 * t;
            float2 v0, v1;
            v0.x = acc[mi][ni][0]; v0.y = acc[mi][ni][1];
            v1.x = acc[mi][ni][2]; v1.y = acc[mi][ni][3];
            *reinterpret_cast<float2*>(out + (size_t)r0 * D_DIM + c0)       = v0;
            *reinterpret_cast<float2*>(out + (size_t)(r0 + 8) * D_DIM + c0) = v1;
        }
    }
}

// ---------------------------------------------------------------------------
extern "C" void kernel_launch(void* const* d_in, const int* in_sizes, int n_in,
                              void* d_out, int out_size) {
    const float* x  = (const float*)d_in[0];
    const float* Wq = (const float*)d_in[1];
    const float* Wk = (const float*)d_in[2];
    const float* Wv = (const float*)d_in[3];
    const float* Wo = (const float*)d_in[4];
    const float* A  = (const float*)d_in[5];
    const float* B  = (const float*)d_in[6];
    const float* C  = (const float*)d_in[7];

    cudaFuncSetAttribute(gemm_f16_kernel, cudaFuncAttributeMaxDynamicSharedMemorySize,
                         SMEM_BYTES);

    weff_kernel<<<dim3(D_DIM / 32, D_DIM / 32), 256>>>(Wq, Wk, Wv, Wo, A, B, C);
    gemm_f16_kernel<<<dim3(D_DIM / BN, MTOT / BM), 256, SMEM_BYTES>>>(x, (float*)d_out);
}